// round 5
// baseline (speedup 1.0000x reference)
#include <cuda_runtime.h>

#define CC   128
#define BKT  8192
#define NMAX 500000

typedef unsigned long long u64;

// ---------------- scratch (__device__ globals; no allocs allowed) ----------
__device__ float    g_q[(size_t)NMAX * CC];      // 256 MB
__device__ float    g_xsum[BKT * CC];
__device__ unsigned g_kkey[BKT * CC];
__device__ unsigned g_vkey[BKT * CC];
__device__ float    g_counts[BKT];
__device__ float    g_kc[BKT * 2 * CC];          // [k_mean | k_max] per bucket
__device__ float    g_vcomb[BKT * CC];           // [v_mean|v_max] @ Wvc + bvc
__device__ unsigned g_or;                        // 0 => ids are int64

// monotonic float<->uint mapping for atomicMax on floats
__device__ __forceinline__ unsigned fenc(float f) {
    unsigned u = __float_as_uint(f);
    return (u & 0x80000000u) ? ~u : (u | 0x80000000u);
}
__device__ __forceinline__ float fdec(unsigned e) {
    return (e & 0x80000000u) ? __uint_as_float(e ^ 0x80000000u)
                             : __uint_as_float(~e);
}
__device__ __forceinline__ int get_id(const void* ids, int i, bool is64) {
    return is64 ? (int)((const long long*)ids)[i] : ((const int*)ids)[i];
}

// packed f32x2 helpers
__device__ __forceinline__ u64 ffma2(u64 a, u64 b, u64 c) {
    u64 d;
    asm("fma.rn.f32x2 %0, %1, %2, %3;" : "=l"(d) : "l"(a), "l"(b), "l"(c));
    return d;
}
__device__ __forceinline__ float2 u2f(u64 v) {
    float2 f;
    asm("mov.b64 {%0, %1}, %2;" : "=f"(f.x), "=f"(f.y) : "l"(v));
    return f;
}

// ---------------- init ------------------------------------------------------
__global__ void k_init() {
    size_t i = (size_t)blockIdx.x * blockDim.x + threadIdx.x;
    size_t stride = (size_t)gridDim.x * blockDim.x;
    for (size_t t = i; t < (size_t)BKT * CC; t += stride) {
        g_xsum[t] = 0.0f; g_kkey[t] = 0u; g_vkey[t] = 0u;
    }
    for (size_t t = i; t < BKT; t += stride) g_counts[t] = 0.0f;
    if (i == 0) g_or = 0u;
}

// ---------------- id dtype detection ---------------------------------------
// OR of odd 32-bit words in the first nwords words. int64 ids (<8192): high
// halves are 0 -> OR==0. int32 ids: odd words are random ids -> OR!=0 w.h.p.
__global__ void k_detect(const unsigned* __restrict__ w, int nwords) {
    unsigned acc = 0;
    int gid = blockIdx.x * blockDim.x + threadIdx.x;
    int stride = gridDim.x * blockDim.x;
    for (int t = 1 + 2 * gid; t < nwords; t += 2 * stride) acc |= w[t];
    for (int o = 16; o; o >>= 1) acc |= __shfl_xor_sync(0xFFFFFFFFu, acc, o);
    if ((threadIdx.x & 31) == 0 && acc) atomicOr(&g_or, acc);
}

// ---------------- phase 1: qkv GEMM + reductions ----------------------------
// tile 128 rows x 128 cols, 256 threads, micro-tile 8 rows (4 pairs) x 8 cols.
// xsT : transposed x tile [k][r], stride 130 (even -> aligned LDS.64 row pairs)
// wdup: weight chunk [kk:32][col-duplicated:256 + 8 pad] -> (w,w) u64 operands
__global__ void __launch_bounds__(256, 2)
k_qkv(const float* __restrict__ x, const void* __restrict__ ids,
      const float* __restrict__ Wq, const float* __restrict__ bq,
      const float* __restrict__ Wk, const float* __restrict__ bk,
      const float* __restrict__ Wv, const float* __restrict__ bv, int n) {
    extern __shared__ float sm[];
    float* xsT  = sm;                 // 128*130 floats
    float* wdup = sm + 128 * 130;     // 32*264 floats
    __shared__ int ids_s[128];

    const bool is64 = (g_or == 0u);
    const int tid = threadIdx.x;
    const int row0 = blockIdx.x * 128;

    if (tid < 128) {
        int r = row0 + tid;
        ids_s[tid] = (r < n) ? get_id(ids, r, is64) : -1;
    }
    for (int t = tid; t < 128 * 32; t += 256) {
        int r = t >> 5, c4 = t & 31;
        float4 v = make_float4(0.f, 0.f, 0.f, 0.f);
        if (row0 + r < n) v = ((const float4*)x)[(size_t)(row0 + r) * 32 + c4];
        xsT[(c4 * 4 + 0) * 130 + r] = v.x;
        xsT[(c4 * 4 + 1) * 130 + r] = v.y;
        xsT[(c4 * 4 + 2) * 130 + r] = v.z;
        xsT[(c4 * 4 + 3) * 130 + r] = v.w;
    }

    const int c0 = (tid & 15) * 8;     // 8 cols
    const int r0 = (tid >> 4) * 8;     // 8 rows = 4 pairs
    const float* Ws[3] = {Wq, Wk, Wv};
    const float* Bs[3] = {bq, bk, bv};

    for (int mm = 0; mm < 3; mm++) {
        u64 acc[4][8];
        #pragma unroll
        for (int p = 0; p < 4; p++)
            #pragma unroll
            for (int j = 0; j < 8; j++) acc[p][j] = 0ull;

        for (int kb = 0; kb < 4; kb++) {
            __syncthreads();  // prior chunk reads done (and tile loads on first)
            for (int t = tid; t < 32 * 32; t += 256) {
                int r = t >> 5, c4 = t & 31;
                float4 v = ((const float4*)Ws[mm])[(kb * 32 + r) * 32 + c4];
                *(float4*)&wdup[r * 264 + c4 * 8]     = make_float4(v.x, v.x, v.y, v.y);
                *(float4*)&wdup[r * 264 + c4 * 8 + 4] = make_float4(v.z, v.z, v.w, v.w);
            }
            __syncthreads();

            for (int kk = 0; kk < 32; kk++) {
                int k = kb * 32 + kk;
                u64 xp[4];
                #pragma unroll
                for (int p = 0; p < 4; p++)
                    xp[p] = *(const u64*)&xsT[k * 130 + r0 + 2 * p];
                const float* wrow = &wdup[kk * 264 + 2 * c0];
                u64 w[8];
                #pragma unroll
                for (int j4 = 0; j4 < 4; j4++) {
                    ulonglong2 ww = *(const ulonglong2*)&wrow[4 * j4];
                    w[2 * j4] = ww.x; w[2 * j4 + 1] = ww.y;
                }
                #pragma unroll
                for (int p = 0; p < 4; p++)
                    #pragma unroll
                    for (int j = 0; j < 8; j++)
                        acc[p][j] = ffma2(xp[p], w[j], acc[p][j]);
            }
        }

        float bb[8];
        #pragma unroll
        for (int j = 0; j < 8; j++) bb[j] = __ldg(&Bs[mm][c0 + j]);

        #pragma unroll
        for (int p = 0; p < 4; p++) {
            float lo[8], hi[8];
            #pragma unroll
            for (int j = 0; j < 8; j++) {
                float2 f = u2f(acc[p][j]);
                lo[j] = f.x + bb[j];
                hi[j] = f.y + bb[j];
            }
            int ra = r0 + 2 * p, rb = ra + 1;
            if (mm == 0) {
                if (row0 + ra < n) {
                    *(float4*)&g_q[(size_t)(row0 + ra) * 128 + c0]     = make_float4(lo[0], lo[1], lo[2], lo[3]);
                    *(float4*)&g_q[(size_t)(row0 + ra) * 128 + c0 + 4] = make_float4(lo[4], lo[5], lo[6], lo[7]);
                }
                if (row0 + rb < n) {
                    *(float4*)&g_q[(size_t)(row0 + rb) * 128 + c0]     = make_float4(hi[0], hi[1], hi[2], hi[3]);
                    *(float4*)&g_q[(size_t)(row0 + rb) * 128 + c0 + 4] = make_float4(hi[4], hi[5], hi[6], hi[7]);
                }
            } else {
                unsigned* keys = (mm == 1) ? g_kkey : g_vkey;
                int ba = ids_s[ra], bbk = ids_s[rb];
                if (ba >= 0) {
                    unsigned* pk = keys + (size_t)ba * 128 + c0;
                    #pragma unroll
                    for (int j = 0; j < 8; j++) atomicMax(&pk[j], fenc(lo[j]));
                }
                if (bbk >= 0) {
                    unsigned* pk = keys + (size_t)bbk * 128 + c0;
                    #pragma unroll
                    for (int j = 0; j < 8; j++) atomicMax(&pk[j], fenc(hi[j]));
                }
            }
        }
    }

    // counts + x_sum (xsT never overwritten)
    #pragma unroll
    for (int i = 0; i < 8; i++) {
        int r = r0 + i;
        int b = ids_s[r];
        if (b >= 0) {
            #pragma unroll
            for (int j = 0; j < 8; j++)
                atomicAdd(&g_xsum[(size_t)b * 128 + c0 + j], xsT[(c0 + j) * 130 + r]);
            if ((tid & 15) == 0) atomicAdd(&g_counts[b], 1.0f);
        }
    }
}

// ---------------- phase 2: centroid finalize + per-bucket Wvc GEMM ----------
// k_sum[b] = x_sum[b] @ Wk + counts[b]*bk (linearity). Then
// vcomb[b] = [v_mean|v_max] @ Wvc + bvc  (moved from per-row to per-bucket!).
__global__ void __launch_bounds__(256)
k_cent(const float* __restrict__ Wk,  const float* __restrict__ bk,
       const float* __restrict__ Wv,  const float* __restrict__ bv,
       const float* __restrict__ Wvc, const float* __restrict__ bvc) {
    __shared__ float vt[2][256];
    int tid = threadIdx.x;
    int bl = tid >> 7, c = tid & 127;
    int b = blockIdx.x * 2 + bl;

    float cnt = g_counts[b];
    float inv = 1.0f / fmaxf(cnt, 1.0f);
    const float* xs = &g_xsum[(size_t)b * 128];
    float ak = 0.0f, av = 0.0f;
    #pragma unroll 4
    for (int k = 0; k < 128; k++) {
        float xv = xs[k];
        ak = fmaf(xv, __ldg(&Wk[k * 128 + c]), ak);
        av = fmaf(xv, __ldg(&Wv[k * 128 + c]), av);
    }
    float kmean = (ak + cnt * __ldg(&bk[c])) * inv;
    float vmean = (av + cnt * __ldg(&bv[c])) * inv;
    bool ne = cnt > 0.0f;
    float kmax = ne ? fdec(g_kkey[(size_t)b * 128 + c]) : 0.0f;
    float vmax = ne ? fdec(g_vkey[(size_t)b * 128 + c]) : 0.0f;

    g_kc[(size_t)b * 256 + c]       = kmean;
    g_kc[(size_t)b * 256 + 128 + c] = kmax;
    vt[bl][c]       = vmean;
    vt[bl][128 + c] = vmax;
    __syncthreads();

    float a = 0.0f;
    #pragma unroll 4
    for (int k = 0; k < 256; k++)
        a = fmaf(vt[bl][k], __ldg(&Wvc[k * 128 + c]), a);
    g_vcomb[(size_t)b * 128 + c] = a + __ldg(&bvc[c]);
}

// ---------------- phase 3: fused gate/output chain --------------------------
// tile 128 rows, 256 threads, micro 16 rows (8 pairs) x 4 cols, f32x2 FMA.
// Transposed activation tiles -> LDS.64 row-pair operands; duplicated weights.
// smem: interT 256x132 | h1T 128x132 | wdup 16x264 = 219648 B.
#define ITS 132
__global__ void __launch_bounds__(256)
k_fused(const void* __restrict__ ids,
        const float* __restrict__ Wg1, const float* __restrict__ bg1,
        const float* __restrict__ Wg2, const float* __restrict__ bg2,
        const float* __restrict__ Wp,  const float* __restrict__ bp,
        float* __restrict__ out, int n) {
    extern __shared__ float sm[];
    float* interT = sm;                      // [k:256][r:128]; tbufT later
    float* h1T    = sm + 256 * ITS;          // [k:128][r:128]
    float* wdup   = h1T + 128 * ITS;         // [kk:16][264]
    __shared__ int ids_s[128];

    const bool is64 = (g_or == 0u);
    const int tid = threadIdx.x;
    const int row0 = blockIdx.x * 128;
    const float scale = 0.17677669529663687f;   // (128/4)^-0.5

    if (tid < 128) {
        int r = row0 + tid;
        ids_s[tid] = (r < n) ? get_id(ids, r, is64) : -1;
    }
    __syncthreads();

    // stage a: interT[k][r] = q[r][k&127] * kc[b][k] * scale
    for (int t = tid; t < 128 * 64; t += 256) {
        int r = t >> 6, k4 = t & 63;
        int b = ids_s[r];
        float4 q = make_float4(0.f, 0.f, 0.f, 0.f), kc = q;
        if (b >= 0) {
            q  = ((const float4*)g_q)[(size_t)(row0 + r) * 32 + (k4 & 31)];
            kc = ((const float4*)g_kc)[(size_t)b * 64 + k4];
        }
        interT[(k4 * 4 + 0) * ITS + r] = q.x * kc.x * scale;
        interT[(k4 * 4 + 1) * ITS + r] = q.y * kc.y * scale;
        interT[(k4 * 4 + 2) * ITS + r] = q.z * kc.z * scale;
        interT[(k4 * 4 + 3) * ITS + r] = q.w * kc.w * scale;
    }

    const int c0 = (tid & 31) * 4;      // 4 cols
    const int r0 = (tid >> 5) * 16;     // 16 rows = 8 pairs

    // ---- stage b: h1 = relu(inter @ Wg1 + bg1), K=256 ----
    {
        u64 acc[8][4];
        #pragma unroll
        for (int p = 0; p < 8; p++)
            #pragma unroll
            for (int j = 0; j < 4; j++) acc[p][j] = 0ull;

        for (int kb = 0; kb < 16; kb++) {
            __syncthreads();
            for (int t = tid; t < 16 * 32; t += 256) {
                int r = t >> 5, c4 = t & 31;
                float4 v = ((const float4*)Wg1)[(kb * 16 + r) * 32 + c4];
                *(float4*)&wdup[r * 264 + c4 * 8]     = make_float4(v.x, v.x, v.y, v.y);
                *(float4*)&wdup[r * 264 + c4 * 8 + 4] = make_float4(v.z, v.z, v.w, v.w);
            }
            __syncthreads();
            for (int kk = 0; kk < 16; kk++) {
                int k = kb * 16 + kk;
                ulonglong2 w01 = *(const ulonglong2*)&wdup[kk * 264 + 2 * c0];
                ulonglong2 w23 = *(const ulonglong2*)&wdup[kk * 264 + 2 * c0 + 4];
                u64 w[4] = {w01.x, w01.y, w23.x, w23.y};
                #pragma unroll
                for (int p = 0; p < 8; p++) {
                    u64 xp = *(const u64*)&interT[k * ITS + r0 + 2 * p];
                    #pragma unroll
                    for (int j = 0; j < 4; j++) acc[p][j] = ffma2(xp, w[j], acc[p][j]);
                }
            }
        }
        float4 b4 = *(const float4*)&bg1[c0];
        float bb[4] = {b4.x, b4.y, b4.z, b4.w};
        #pragma unroll
        for (int p = 0; p < 8; p++)
            #pragma unroll
            for (int j = 0; j < 4; j++) {
                float2 f = u2f(acc[p][j]);
                float2 res = make_float2(fmaxf(f.x + bb[j], 0.0f),
                                         fmaxf(f.y + bb[j], 0.0f));
                *(float2*)&h1T[(c0 + j) * ITS + r0 + 2 * p] = res;
            }
    }

    // ---- stage d: gate = sigmoid(h1 @ Wg2 + bg2); tbuf = gate * vcomb ----
    {
        u64 acc[8][4];
        #pragma unroll
        for (int p = 0; p < 8; p++)
            #pragma unroll
            for (int j = 0; j < 4; j++) acc[p][j] = 0ull;

        for (int kb = 0; kb < 8; kb++) {
            __syncthreads();  // first iter: all h1T writes done
            for (int t = tid; t < 16 * 32; t += 256) {
                int r = t >> 5, c4 = t & 31;
                float4 v = ((const float4*)Wg2)[(kb * 16 + r) * 32 + c4];
                *(float4*)&wdup[r * 264 + c4 * 8]     = make_float4(v.x, v.x, v.y, v.y);
                *(float4*)&wdup[r * 264 + c4 * 8 + 4] = make_float4(v.z, v.z, v.w, v.w);
            }
            __syncthreads();
            for (int kk = 0; kk < 16; kk++) {
                int k = kb * 16 + kk;
                ulonglong2 w01 = *(const ulonglong2*)&wdup[kk * 264 + 2 * c0];
                ulonglong2 w23 = *(const ulonglong2*)&wdup[kk * 264 + 2 * c0 + 4];
                u64 w[4] = {w01.x, w01.y, w23.x, w23.y};
                #pragma unroll
                for (int p = 0; p < 8; p++) {
                    u64 xp = *(const u64*)&h1T[k * ITS + r0 + 2 * p];
                    #pragma unroll
                    for (int j = 0; j < 4; j++) acc[p][j] = ffma2(xp, w[j], acc[p][j]);
                }
            }
        }
        float4 b4 = *(const float4*)&bg2[c0];
        float bb[4] = {b4.x, b4.y, b4.z, b4.w};
        #pragma unroll
        for (int p = 0; p < 8; p++) {
            int ra = r0 + 2 * p, rb = ra + 1;
            int ba = ids_s[ra], bbk = ids_s[rb];
            float4 va = make_float4(0.f, 0.f, 0.f, 0.f), vb = va;
            if (ba >= 0)  va = *(const float4*)&g_vcomb[(size_t)ba * 128 + c0];
            if (bbk >= 0) vb = *(const float4*)&g_vcomb[(size_t)bbk * 128 + c0];
            float vaa[4] = {va.x, va.y, va.z, va.w};
            float vba[4] = {vb.x, vb.y, vb.z, vb.w};
            #pragma unroll
            for (int j = 0; j < 4; j++) {
                float2 f = u2f(acc[p][j]);
                float ga = 1.0f / (1.0f + __expf(-(f.x + bb[j])));
                float gb = 1.0f / (1.0f + __expf(-(f.y + bb[j])));
                float2 res = make_float2(ga * vaa[j], gb * vba[j]);
                *(float2*)&interT[(c0 + j) * ITS + r0 + 2 * p] = res;  // tbufT
            }
        }
    }

    // ---- stage e: out = tbuf @ Wp + bp, K=128 ----
    {
        u64 acc[8][4];
        #pragma unroll
        for (int p = 0; p < 8; p++)
            #pragma unroll
            for (int j = 0; j < 4; j++) acc[p][j] = 0ull;

        for (int kb = 0; kb < 8; kb++) {
            __syncthreads();  // first iter: all tbufT writes done
            for (int t = tid; t < 16 * 32; t += 256) {
                int r = t >> 5, c4 = t & 31;
                float4 v = ((const float4*)Wp)[(kb * 16 + r) * 32 + c4];
                *(float4*)&wdup[r * 264 + c4 * 8]     = make_float4(v.x, v.x, v.y, v.y);
                *(float4*)&wdup[r * 264 + c4 * 8 + 4] = make_float4(v.z, v.z, v.w, v.w);
            }
            __syncthreads();
            for (int kk = 0; kk < 16; kk++) {
                int k = kb * 16 + kk;
                ulonglong2 w01 = *(const ulonglong2*)&wdup[kk * 264 + 2 * c0];
                ulonglong2 w23 = *(const ulonglong2*)&wdup[kk * 264 + 2 * c0 + 4];
                u64 w[4] = {w01.x, w01.y, w23.x, w23.y};
                #pragma unroll
                for (int p = 0; p < 8; p++) {
                    u64 xp = *(const u64*)&interT[k * ITS + r0 + 2 * p];
                    #pragma unroll
                    for (int j = 0; j < 4; j++) acc[p][j] = ffma2(xp, w[j], acc[p][j]);
                }
            }
        }
        float4 b4 = *(const float4*)&bp[c0];
        float bb[4] = {b4.x, b4.y, b4.z, b4.w};
        #pragma unroll
        for (int p = 0; p < 8; p++) {
            int ra = row0 + r0 + 2 * p, rb = ra + 1;
            float lo[4], hi[4];
            #pragma unroll
            for (int j = 0; j < 4; j++) {
                float2 f = u2f(acc[p][j]);
                lo[j] = f.x + bb[j];
                hi[j] = f.y + bb[j];
            }
            if (ra < n)
                *(float4*)&out[(size_t)ra * 128 + c0] = make_float4(lo[0], lo[1], lo[2], lo[3]);
            if (rb < n)
                *(float4*)&out[(size_t)rb * 128 + c0] = make_float4(hi[0], hi[1], hi[2], hi[3]);
        }
    }
}

// ---------------- launch ----------------------------------------------------
extern "C" void kernel_launch(void* const* d_in, const int* in_sizes, int n_in,
                              void* d_out, int out_size) {
    const float* x   = (const float*)d_in[0];
    const void*  ids = d_in[1];
    // d_in[2] = total_buckets (constant 8192, unused)
    const float *Wq = (const float*)d_in[3],  *bq = (const float*)d_in[4];
    const float *Wk = (const float*)d_in[5],  *bk = (const float*)d_in[6];
    const float *Wv = (const float*)d_in[7],  *bv = (const float*)d_in[8];
    const float *Wg1 = (const float*)d_in[9], *bg1 = (const float*)d_in[10];
    const float *Wg2 = (const float*)d_in[11], *bg2 = (const float*)d_in[12];
    const float *Wvc = (const float*)d_in[13], *bvc = (const float*)d_in[14];
    const float *Wp  = (const float*)d_in[15], *bp  = (const float*)d_in[16];
    float* out = (float*)d_out;

    const int n = in_sizes[0] / CC;

    const int SM_QKV   = (128 * 130 + 32 * 264) * 4;                // 100352
    const int SM_FUSED = (256 * ITS + 128 * ITS + 16 * 264) * 4;    // 219648

    static int smem_set = 0;
    if (!smem_set) {
        cudaFuncSetAttribute(k_qkv,   cudaFuncAttributeMaxDynamicSharedMemorySize, SM_QKV);
        cudaFuncSetAttribute(k_fused, cudaFuncAttributeMaxDynamicSharedMemorySize, SM_FUSED);
        smem_set = 1;
    }

    k_init<<<512, 256>>>();
    k_detect<<<256, 256>>>((const unsigned*)ids, in_sizes[1]);

    int g1 = (n + 127) / 128;
    k_qkv<<<g1, 256, SM_QKV>>>(x, ids, Wq, bq, Wk, bk, Wv, bv, n);

    k_cent<<<BKT / 2, 256>>>(Wk, bk, Wv, bv, Wvc, bvc);

    k_fused<<<g1, 256, SM_FUSED>>>(ids, Wg1, bg1, Wg2, bg2, Wp, bp, out, n);
}

// round 6
// speedup vs baseline: 1.4155x; 1.4155x over previous
#include <cuda_runtime.h>

#define CC   128
#define BKT  8192
#define NMAX 500000

// ---------------- scratch (__device__ globals; no allocs allowed) ----------
__device__ float    g_q[(size_t)NMAX * CC];      // 256 MB
__device__ float    g_xsum[BKT * CC];
__device__ unsigned g_kkey[BKT * CC];
__device__ unsigned g_vkey[BKT * CC];
__device__ float    g_counts[BKT];
__device__ float    g_kc[BKT * 2 * CC];          // [k_mean | k_max] per bucket
__device__ float    g_vcomb[BKT * CC];           // [v_mean|v_max] @ Wvc + bvc
__device__ unsigned g_or;                        // 0 => ids are int64

// monotonic float<->uint mapping for atomicMax on floats
__device__ __forceinline__ unsigned fenc(float f) {
    unsigned u = __float_as_uint(f);
    return (u & 0x80000000u) ? ~u : (u | 0x80000000u);
}
__device__ __forceinline__ float fdec(unsigned e) {
    return (e & 0x80000000u) ? __uint_as_float(e ^ 0x80000000u)
                             : __uint_as_float(~e);
}
__device__ __forceinline__ int get_id(const void* ids, int i, bool is64) {
    return is64 ? (int)((const long long*)ids)[i] : ((const int*)ids)[i];
}

// ---------------- init ------------------------------------------------------
__global__ void k_init() {
    size_t i = (size_t)blockIdx.x * blockDim.x + threadIdx.x;
    size_t stride = (size_t)gridDim.x * blockDim.x;
    for (size_t t = i; t < (size_t)BKT * CC; t += stride) {
        g_xsum[t] = 0.0f; g_kkey[t] = 0u; g_vkey[t] = 0u;
    }
    for (size_t t = i; t < BKT; t += stride) g_counts[t] = 0.0f;
    if (i == 0) g_or = 0u;
}

// ---------------- id dtype detection ---------------------------------------
// OR of odd 32-bit words. int64 ids (<8192): high halves are 0 -> OR==0.
// int32 ids: odd words are random ids -> OR!=0 w.h.p.
__global__ void k_detect(const unsigned* __restrict__ w, int nwords) {
    unsigned acc = 0;
    int gid = blockIdx.x * blockDim.x + threadIdx.x;
    int stride = gridDim.x * blockDim.x;
    for (int t = 1 + 2 * gid; t < nwords; t += 2 * stride) acc |= w[t];
    for (int o = 16; o; o >>= 1) acc |= __shfl_xor_sync(0xFFFFFFFFu, acc, o);
    if ((threadIdx.x & 31) == 0 && acc) atomicOr(&g_or, acc);
}

// ---------------- phase 1: qkv GEMM + reductions ----------------------------
// tile 128 rows x 128 cols, 256 threads, thread computes 8x8 (round-4 micro).
// xsT: transposed x tile [k][r], stride 129. ws: 32-k weight chunk, stride 132.
__global__ void __launch_bounds__(256)
k_qkv(const float* __restrict__ x, const void* __restrict__ ids,
      const float* __restrict__ Wq, const float* __restrict__ bq,
      const float* __restrict__ Wk, const float* __restrict__ bk,
      const float* __restrict__ Wv, const float* __restrict__ bv, int n) {
    extern __shared__ float sm[];
    float* xsT = sm;               // 128*129
    float* ws  = sm + 128 * 129;   // 32*132
    __shared__ int ids_s[128];

    const bool is64 = (g_or == 0u);
    const int tid = threadIdx.x;
    const int row0 = blockIdx.x * 128;

    if (tid < 128) {
        int r = row0 + tid;
        ids_s[tid] = (r < n) ? get_id(ids, r, is64) : -1;
    }
    for (int t = tid; t < 128 * 32; t += 256) {
        int r = t >> 5, c4 = t & 31;
        float4 v = make_float4(0.f, 0.f, 0.f, 0.f);
        if (row0 + r < n) v = ((const float4*)x)[(size_t)(row0 + r) * 32 + c4];
        xsT[(c4 * 4 + 0) * 129 + r] = v.x;
        xsT[(c4 * 4 + 1) * 129 + r] = v.y;
        xsT[(c4 * 4 + 2) * 129 + r] = v.z;
        xsT[(c4 * 4 + 3) * 129 + r] = v.w;
    }

    const int rT = tid >> 4;          // 0..15, rows rT + 16*i
    const int c0 = (tid & 15) * 8;    // 8 cols
    const float* Ws[3] = {Wq, Wk, Wv};
    const float* Bs[3] = {bq, bk, bv};

    for (int mm = 0; mm < 3; mm++) {
        float acc[8][8];
        #pragma unroll
        for (int i = 0; i < 8; i++)
            #pragma unroll
            for (int j = 0; j < 8; j++) acc[i][j] = 0.0f;

        for (int kb = 0; kb < 4; kb++) {
            __syncthreads();   // prior reads of ws done; first also covers tile loads
            for (int t = tid; t < 32 * 32; t += 256) {
                int r = t >> 5, c4 = t & 31;
                ((float4*)&ws[r * 132])[c4] = ((const float4*)Ws[mm])[(kb * 32 + r) * 32 + c4];
            }
            __syncthreads();

            for (int kk = 0; kk < 32; kk++) {
                int k = kb * 32 + kk;
                float xv[8];
                #pragma unroll
                for (int i = 0; i < 8; i++) xv[i] = xsT[k * 129 + rT + 16 * i];
                float4 w0 = *(const float4*)&ws[kk * 132 + c0];
                float4 w1 = *(const float4*)&ws[kk * 132 + c0 + 4];
                float wr[8] = {w0.x, w0.y, w0.z, w0.w, w1.x, w1.y, w1.z, w1.w};
                #pragma unroll
                for (int i = 0; i < 8; i++)
                    #pragma unroll
                    for (int j = 0; j < 8; j++)
                        acc[i][j] = fmaf(xv[i], wr[j], acc[i][j]);
            }
        }

        float bb[8];
        #pragma unroll
        for (int j = 0; j < 8; j++) bb[j] = __ldg(&Bs[mm][c0 + j]);
        #pragma unroll
        for (int i = 0; i < 8; i++)
            #pragma unroll
            for (int j = 0; j < 8; j++) acc[i][j] += bb[j];

        if (mm == 0) {
            #pragma unroll
            for (int i = 0; i < 8; i++) {
                int r = rT + 16 * i, grow = row0 + r;
                if (grow < n) {
                    *(float4*)&g_q[(size_t)grow * 128 + c0]     = make_float4(acc[i][0], acc[i][1], acc[i][2], acc[i][3]);
                    *(float4*)&g_q[(size_t)grow * 128 + c0 + 4] = make_float4(acc[i][4], acc[i][5], acc[i][6], acc[i][7]);
                }
            }
        } else {
            unsigned* keys = (mm == 1) ? g_kkey : g_vkey;
            #pragma unroll
            for (int i = 0; i < 8; i++) {
                int r = rT + 16 * i;
                int b = ids_s[r];
                if (b >= 0) {
                    unsigned* p = keys + (size_t)b * 128 + c0;
                    #pragma unroll
                    for (int j = 0; j < 8; j++) atomicMax(&p[j], fenc(acc[i][j]));
                }
            }
        }
    }

    // counts + x_sum (xsT never overwritten)
    #pragma unroll
    for (int i = 0; i < 8; i++) {
        int r = rT + 16 * i;
        int b = ids_s[r];
        if (b >= 0) {
            #pragma unroll
            for (int j = 0; j < 8; j++)
                atomicAdd(&g_xsum[(size_t)b * 128 + c0 + j], xsT[(c0 + j) * 129 + r]);
            if (c0 == 0) atomicAdd(&g_counts[b], 1.0f);
        }
    }
}

// ---------------- phase 2: centroid finalize + per-bucket Wvc GEMM ----------
// k_sum[b] = x_sum[b] @ Wk + counts[b]*bk (linearity). Then
// vcomb[b] = [v_mean|v_max] @ Wvc + bvc  (per-bucket, not per-row!).
__global__ void __launch_bounds__(256)
k_cent(const float* __restrict__ Wk,  const float* __restrict__ bk,
       const float* __restrict__ Wv,  const float* __restrict__ bv,
       const float* __restrict__ Wvc, const float* __restrict__ bvc) {
    __shared__ float vt[2][256];
    int tid = threadIdx.x;
    int bl = tid >> 7, c = tid & 127;
    int b = blockIdx.x * 2 + bl;

    float cnt = g_counts[b];
    float inv = 1.0f / fmaxf(cnt, 1.0f);
    const float* xs = &g_xsum[(size_t)b * 128];
    float ak = 0.0f, av = 0.0f;
    #pragma unroll 4
    for (int k = 0; k < 128; k++) {
        float xv = xs[k];
        ak = fmaf(xv, __ldg(&Wk[k * 128 + c]), ak);
        av = fmaf(xv, __ldg(&Wv[k * 128 + c]), av);
    }
    float kmean = (ak + cnt * __ldg(&bk[c])) * inv;
    float vmean = (av + cnt * __ldg(&bv[c])) * inv;
    bool ne = cnt > 0.0f;
    float kmax = ne ? fdec(g_kkey[(size_t)b * 128 + c]) : 0.0f;
    float vmax = ne ? fdec(g_vkey[(size_t)b * 128 + c]) : 0.0f;

    g_kc[(size_t)b * 256 + c]       = kmean;
    g_kc[(size_t)b * 256 + 128 + c] = kmax;
    vt[bl][c]       = vmean;
    vt[bl][128 + c] = vmax;
    __syncthreads();

    float a = 0.0f;
    #pragma unroll 4
    for (int k = 0; k < 256; k++)
        a = fmaf(vt[bl][k], __ldg(&Wvc[k * 128 + c]), a);
    g_vcomb[(size_t)b * 128 + c] = a + __ldg(&bvc[c]);
}

// ---------------- phase 3: fused gate/output chain --------------------------
// tile 64 rows, 256 threads; thread = 8 rows x 4 cols (round-4 micro).
// No padding (all reads broadcast or contiguous): inter 64x256 | h1 64x128 |
// wst 32x128 = 114688 B -> 2 CTAs/SM.
__global__ void __launch_bounds__(256, 2)
k_fused(const void* __restrict__ ids,
        const float* __restrict__ Wg1, const float* __restrict__ bg1,
        const float* __restrict__ Wg2, const float* __restrict__ bg2,
        const float* __restrict__ Wp,  const float* __restrict__ bp,
        float* __restrict__ out, int n) {
    extern __shared__ float sm[];
    float* inter = sm;                  // 64*256 ; reused as tbuf
    float* h1    = sm + 64 * 256;       // 64*128
    float* wst   = h1 + 64 * 128;       // 32*128
    __shared__ int ids_s[64];

    const bool is64 = (g_or == 0u);
    const int tid = threadIdx.x;
    const int row0 = blockIdx.x * 64;
    const float scale = 0.17677669529663687f;   // (128/4)^-0.5

    if (tid < 64) {
        int r = row0 + tid;
        ids_s[tid] = (r < n) ? get_id(ids, r, is64) : -1;
    }
    __syncthreads();

    // stage a: inter = [q,q]*kctx*scale
    for (int t = tid; t < 64 * 64; t += 256) {
        int r = t >> 6, c4 = t & 63;
        int b = ids_s[r];
        float4 iv = make_float4(0.f, 0.f, 0.f, 0.f);
        if (b >= 0) {
            float4 qv = ((const float4*)g_q)[(size_t)(row0 + r) * 32 + (c4 & 31)];
            float4 kc = ((const float4*)g_kc)[(size_t)b * 64 + c4];
            iv.x = qv.x * kc.x * scale; iv.y = qv.y * kc.y * scale;
            iv.z = qv.z * kc.z * scale; iv.w = qv.w * kc.w * scale;
        }
        *(float4*)&inter[r * 256 + c4 * 4] = iv;
    }

    const int rT = tid >> 5;          // 0..7, rows rT + 8*i
    const int c0 = (tid & 31) * 4;    // 4 cols

    // stage b: h1 = relu(inter @ Wg1 + bg1), K=256 in 8 chunks of 32
    float acc[8][4];
    #pragma unroll
    for (int i = 0; i < 8; i++)
        #pragma unroll
        for (int j = 0; j < 4; j++) acc[i][j] = 0.0f;
    for (int kb = 0; kb < 8; kb++) {
        __syncthreads();   // first iter also covers stage-a writes
        for (int t = tid; t < 32 * 32; t += 256) {
            int r = t >> 5, c4 = t & 31;
            ((float4*)&wst[r * 128])[c4] = ((const float4*)Wg1)[(kb * 32 + r) * 32 + c4];
        }
        __syncthreads();
        for (int kk = 0; kk < 32; kk++) {
            int k = kb * 32 + kk;
            float4 w = *(const float4*)&wst[kk * 128 + c0];
            #pragma unroll
            for (int i = 0; i < 8; i++) {
                float xv = inter[(rT + 8 * i) * 256 + k];
                acc[i][0] = fmaf(xv, w.x, acc[i][0]);
                acc[i][1] = fmaf(xv, w.y, acc[i][1]);
                acc[i][2] = fmaf(xv, w.z, acc[i][2]);
                acc[i][3] = fmaf(xv, w.w, acc[i][3]);
            }
        }
    }
    {
        float4 b4 = *(const float4*)&bg1[c0];
        float bb[4] = {b4.x, b4.y, b4.z, b4.w};
        #pragma unroll
        for (int i = 0; i < 8; i++)
            #pragma unroll
            for (int j = 0; j < 4; j++)
                h1[(rT + 8 * i) * 128 + c0 + j] = fmaxf(acc[i][j] + bb[j], 0.0f);
    }

    // stage d: gate = sigmoid(h1 @ Wg2 + bg2); tbuf = gate * vcomb[bucket]
    float gacc[8][4];
    #pragma unroll
    for (int i = 0; i < 8; i++)
        #pragma unroll
        for (int j = 0; j < 4; j++) gacc[i][j] = 0.0f;
    for (int kb = 0; kb < 4; kb++) {
        __syncthreads();   // first iter: all h1 writes done
        for (int t = tid; t < 32 * 32; t += 256) {
            int r = t >> 5, c4 = t & 31;
            ((float4*)&wst[r * 128])[c4] = ((const float4*)Wg2)[(kb * 32 + r) * 32 + c4];
        }
        __syncthreads();
        for (int kk = 0; kk < 32; kk++) {
            int k = kb * 32 + kk;
            float4 w = *(const float4*)&wst[kk * 128 + c0];
            #pragma unroll
            for (int i = 0; i < 8; i++) {
                float xv = h1[(rT + 8 * i) * 128 + k];
                gacc[i][0] = fmaf(xv, w.x, gacc[i][0]);
                gacc[i][1] = fmaf(xv, w.y, gacc[i][1]);
                gacc[i][2] = fmaf(xv, w.z, gacc[i][2]);
                gacc[i][3] = fmaf(xv, w.w, gacc[i][3]);
            }
        }
    }
    {
        float4 b4 = *(const float4*)&bg2[c0];
        float bb[4] = {b4.x, b4.y, b4.z, b4.w};
        #pragma unroll
        for (int i = 0; i < 8; i++) {
            int r = rT + 8 * i;
            int b = ids_s[r];
            float4 vc = make_float4(0.f, 0.f, 0.f, 0.f);
            if (b >= 0) vc = *(const float4*)&g_vcomb[(size_t)b * 128 + c0];
            float vca[4] = {vc.x, vc.y, vc.z, vc.w};
            #pragma unroll
            for (int j = 0; j < 4; j++) {
                float gate = 1.0f / (1.0f + __expf(-(gacc[i][j] + bb[j])));
                inter[r * 256 + c0 + j] = gate * vca[j];  // tbuf (inter reused)
            }
        }
    }

    // stage e: out = tbuf @ Wp + bp, K=128 in 4 chunks of 32
    float oacc[8][4];
    #pragma unroll
    for (int i = 0; i < 8; i++)
        #pragma unroll
        for (int j = 0; j < 4; j++) oacc[i][j] = 0.0f;
    for (int kb = 0; kb < 4; kb++) {
        __syncthreads();   // first iter: all tbuf writes done
        for (int t = tid; t < 32 * 32; t += 256) {
            int r = t >> 5, c4 = t & 31;
            ((float4*)&wst[r * 128])[c4] = ((const float4*)Wp)[(kb * 32 + r) * 32 + c4];
        }
        __syncthreads();
        for (int kk = 0; kk < 32; kk++) {
            int k = kb * 32 + kk;
            float4 w = *(const float4*)&wst[kk * 128 + c0];
            #pragma unroll
            for (int i = 0; i < 8; i++) {
                float xv = inter[(rT + 8 * i) * 256 + k];
                oacc[i][0] = fmaf(xv, w.x, oacc[i][0]);
                oacc[i][1] = fmaf(xv, w.y, oacc[i][1]);
                oacc[i][2] = fmaf(xv, w.z, oacc[i][2]);
                oacc[i][3] = fmaf(xv, w.w, oacc[i][3]);
            }
        }
    }
    {
        float4 b4 = *(const float4*)&bp[c0];
        float bb[4] = {b4.x, b4.y, b4.z, b4.w};
        #pragma unroll
        for (int i = 0; i < 8; i++) {
            int grow = row0 + rT + 8 * i;
            if (grow < n) {
                *(float4*)&out[(size_t)grow * 128 + c0] =
                    make_float4(oacc[i][0] + bb[0], oacc[i][1] + bb[1],
                                oacc[i][2] + bb[2], oacc[i][3] + bb[3]);
            }
        }
    }
}

// ---------------- launch ----------------------------------------------------
extern "C" void kernel_launch(void* const* d_in, const int* in_sizes, int n_in,
                              void* d_out, int out_size) {
    const float* x   = (const float*)d_in[0];
    const void*  ids = d_in[1];
    // d_in[2] = total_buckets (constant 8192, unused)
    const float *Wq = (const float*)d_in[3],  *bq = (const float*)d_in[4];
    const float *Wk = (const float*)d_in[5],  *bk = (const float*)d_in[6];
    const float *Wv = (const float*)d_in[7],  *bv = (const float*)d_in[8];
    const float *Wg1 = (const float*)d_in[9], *bg1 = (const float*)d_in[10];
    const float *Wg2 = (const float*)d_in[11], *bg2 = (const float*)d_in[12];
    const float *Wvc = (const float*)d_in[13], *bvc = (const float*)d_in[14];
    const float *Wp  = (const float*)d_in[15], *bp  = (const float*)d_in[16];
    float* out = (float*)d_out;

    const int n = in_sizes[0] / CC;

    const int SM_QKV   = (128 * 129 + 32 * 132) * 4;               // 82944
    const int SM_FUSED = (64 * 256 + 64 * 128 + 32 * 128) * 4;     // 114688

    static int smem_set = 0;
    if (!smem_set) {
        cudaFuncSetAttribute(k_qkv,   cudaFuncAttributeMaxDynamicSharedMemorySize, SM_QKV);
        cudaFuncSetAttribute(k_fused, cudaFuncAttributeMaxDynamicSharedMemorySize, SM_FUSED);
        smem_set = 1;
    }

    k_init<<<512, 256>>>();
    k_detect<<<256, 256>>>((const unsigned*)ids, in_sizes[1]);

    int g1 = (n + 127) / 128;
    k_qkv<<<g1, 256, SM_QKV>>>(x, ids, Wq, bq, Wk, bk, Wv, bv, n);

    k_cent<<<BKT / 2, 256>>>(Wk, bk, Wv, bv, Wvc, bvc);

    int g3 = (n + 63) / 64;
    k_fused<<<g3, 256, SM_FUSED>>>(ids, Wg1, bg1, Wg2, bg2, Wp, bp, out, n);
}

// round 8
// speedup vs baseline: 1.5343x; 1.0839x over previous
#include <cuda_runtime.h>
#include <cuda_bf16.h>
#include <mma.h>
#include <cstdint>

using namespace nvcuda;

#define CC   128
#define BKT  8192
#define NMAX 500000

// ---------------- scratch (__device__ globals; no allocs allowed) ----------
__device__ float    g_q[(size_t)NMAX * CC];      // 256 MB
__device__ float    g_xsum[BKT * CC];
__device__ unsigned g_kkey[BKT * CC];
__device__ unsigned g_vkey[BKT * CC];
__device__ float    g_counts[BKT];
__device__ float    g_kc[BKT * 2 * CC];          // [k_mean | k_max] per bucket
__device__ float    g_vcomb[BKT * CC];           // [v_mean|v_max] @ Wvc + bvc
__device__ unsigned g_or;                        // 0 => ids are int64

// monotonic float<->uint mapping for atomicMax on floats
__device__ __forceinline__ unsigned fenc(float f) {
    unsigned u = __float_as_uint(f);
    return (u & 0x80000000u) ? ~u : (u | 0x80000000u);
}
__device__ __forceinline__ float fdec(unsigned e) {
    return (e & 0x80000000u) ? __uint_as_float(e ^ 0x80000000u)
                             : __uint_as_float(~e);
}
__device__ __forceinline__ int get_id(const void* ids, int i, bool is64) {
    return is64 ? (int)((const long long*)ids)[i] : ((const int*)ids)[i];
}
__device__ __forceinline__ void bfsplit(float v, __nv_bfloat16& h, __nv_bfloat16& l) {
    h = __float2bfloat16(v);
    l = __float2bfloat16(v - __bfloat162float(h));
}

// ---------------- init ------------------------------------------------------
__global__ void k_init() {
    size_t i = (size_t)blockIdx.x * blockDim.x + threadIdx.x;
    size_t stride = (size_t)gridDim.x * blockDim.x;
    for (size_t t = i; t < (size_t)BKT * CC; t += stride) {
        g_xsum[t] = 0.0f; g_kkey[t] = 0u; g_vkey[t] = 0u;
    }
    for (size_t t = i; t < BKT; t += stride) g_counts[t] = 0.0f;
    if (i == 0) g_or = 0u;
}

// ---------------- id dtype detection ---------------------------------------
// OR of odd 32-bit words. int64 ids (<8192): high halves are 0 -> OR==0.
__global__ void k_detect(const unsigned* __restrict__ w, int nwords) {
    unsigned acc = 0;
    int gid = blockIdx.x * blockDim.x + threadIdx.x;
    int stride = gridDim.x * blockDim.x;
    for (int t = 1 + 2 * gid; t < nwords; t += 2 * stride) acc |= w[t];
    for (int o = 16; o; o >>= 1) acc |= __shfl_xor_sync(0xFFFFFFFFu, acc, o);
    if ((threadIdx.x & 31) == 0 && acc) atomicOr(&g_or, acc);
}

// ---------------- phase 1: wmma bf16-split qkv GEMM + reductions ------------
// CTA tile 128 rows x 128 cols, 256 threads = 8 warps, warp = 32x64 block.
// 3-product split: hi*hi + hi*lo + lo*hi  (error ~ eps_bf16^2).
#define XS_STR 136     // bf16 elements per row (8-row ldmatrix conflict-free)
#define OB_STR 132     // f32 out staging stride
#define SM_QKV_BYTES (4 * 128 * XS_STR * 2 + 128 * OB_STR * 4)   // 206848

__global__ void __launch_bounds__(256)
k_qkv(const float* __restrict__ x, const void* __restrict__ ids,
      const float* __restrict__ Wq, const float* __restrict__ bq,
      const float* __restrict__ Wk, const float* __restrict__ bk,
      const float* __restrict__ Wv, const float* __restrict__ bv, int n) {
    extern __shared__ unsigned char smraw[];
    __nv_bfloat16* xs_hi = (__nv_bfloat16*)smraw;
    __nv_bfloat16* xs_lo = xs_hi + 128 * XS_STR;
    __nv_bfloat16* ws_hi = xs_lo + 128 * XS_STR;
    __nv_bfloat16* ws_lo = ws_hi + 128 * XS_STR;
    float* outb = (float*)(ws_lo + 128 * XS_STR);
    __shared__ int ids_s[128];
    __shared__ float s_b[3][128];

    const bool is64 = (g_or == 0u);
    const int tid = threadIdx.x;
    const int wid = tid >> 5;
    const int row0 = blockIdx.x * 128;
    const int wr = wid >> 1;          // 0..3 : rows wr*32
    const int wc = wid & 1;           // 0..1 : cols wc*64

    if (tid < 128) {
        int r = row0 + tid;
        ids_s[tid] = (r < n) ? get_id(ids, r, is64) : -1;
        s_b[0][tid] = bq[tid]; s_b[1][tid] = bk[tid]; s_b[2][tid] = bv[tid];
    }

    // x tile -> bf16 hi/lo (row-major, stride XS_STR)
    for (int t = tid; t < 128 * 32; t += 256) {
        int r = t >> 5, c4 = t & 31;
        float4 v = make_float4(0.f, 0.f, 0.f, 0.f);
        if (row0 + r < n) v = ((const float4*)x)[(size_t)(row0 + r) * 32 + c4];
        float vv[4] = {v.x, v.y, v.z, v.w};
        #pragma unroll
        for (int j = 0; j < 4; j++) {
            __nv_bfloat16 h, l;
            bfsplit(vv[j], h, l);
            xs_hi[r * XS_STR + c4 * 4 + j] = h;
            xs_lo[r * XS_STR + c4 * 4 + j] = l;
        }
    }

    const float* Ws[3] = {Wq, Wk, Wv};
    const int ep_r = tid >> 1;              // epilogue row
    const int ep_c0 = (tid & 1) * 64;       // epilogue col start

    for (int mm = 0; mm < 3; mm++) {
        // (1) weight -> bf16 hi/lo split in smem [k][c], stride XS_STR
        for (int t = tid; t < 4096; t += 256) {
            int k = t >> 5, c4 = t & 31;
            float4 v = ((const float4*)Ws[mm])[t];
            float vv[4] = {v.x, v.y, v.z, v.w};
            #pragma unroll
            for (int j = 0; j < 4; j++) {
                __nv_bfloat16 h, l;
                bfsplit(vv[j], h, l);
                ws_hi[k * XS_STR + c4 * 4 + j] = h;
                ws_lo[k * XS_STR + c4 * 4 + j] = l;
            }
        }
        __syncthreads();   // (2) ws ready; mm==0: xs ready; outb epilogue reads done

        // (3) wmma mainloop
        wmma::fragment<wmma::accumulator, 16, 16, 16, float> acc[2][4];
        #pragma unroll
        for (int i = 0; i < 2; i++)
            #pragma unroll
            for (int j = 0; j < 4; j++) wmma::fill_fragment(acc[i][j], 0.0f);

        #pragma unroll
        for (int ks = 0; ks < 8; ks++) {
            int k = ks * 16;
            wmma::fragment<wmma::matrix_a, 16, 16, 16, __nv_bfloat16, wmma::row_major> ah[2], al[2];
            #pragma unroll
            for (int i = 0; i < 2; i++) {
                wmma::load_matrix_sync(ah[i], &xs_hi[(wr * 32 + i * 16) * XS_STR + k], XS_STR);
                wmma::load_matrix_sync(al[i], &xs_lo[(wr * 32 + i * 16) * XS_STR + k], XS_STR);
            }
            #pragma unroll
            for (int j = 0; j < 4; j++) {
                wmma::fragment<wmma::matrix_b, 16, 16, 16, __nv_bfloat16, wmma::row_major> bh, bl;
                wmma::load_matrix_sync(bh, &ws_hi[k * XS_STR + wc * 64 + j * 16], XS_STR);
                wmma::load_matrix_sync(bl, &ws_lo[k * XS_STR + wc * 64 + j * 16], XS_STR);
                #pragma unroll
                for (int i = 0; i < 2; i++) {
                    wmma::mma_sync(acc[i][j], ah[i], bh, acc[i][j]);
                    wmma::mma_sync(acc[i][j], ah[i], bl, acc[i][j]);
                    wmma::mma_sync(acc[i][j], al[i], bh, acc[i][j]);
                }
            }
        }

        // (4) stage to smem
        #pragma unroll
        for (int i = 0; i < 2; i++)
            #pragma unroll
            for (int j = 0; j < 4; j++)
                wmma::store_matrix_sync(&outb[(wr * 32 + i * 16) * OB_STR + wc * 64 + j * 16],
                                        acc[i][j], OB_STR, wmma::mem_row_major);
        __syncthreads();   // (5)

        // (6) epilogue: thread = half row
        if (mm == 0) {
            int grow = row0 + ep_r;
            if (grow < n) {
                float* qp = &g_q[(size_t)grow * 128];
                #pragma unroll
                for (int c = 0; c < 64; c += 4) {
                    int cc = ep_c0 + c;
                    float4 o = *(const float4*)&outb[ep_r * OB_STR + cc];
                    *(float4*)&qp[cc] = make_float4(o.x + s_b[0][cc], o.y + s_b[0][cc + 1],
                                                    o.z + s_b[0][cc + 2], o.w + s_b[0][cc + 3]);
                }
            }
        } else {
            int b = ids_s[ep_r];
            if (b >= 0) {
                unsigned* p = ((mm == 1) ? g_kkey : g_vkey) + (size_t)b * 128;
                #pragma unroll 8
                for (int c = 0; c < 64; c++) {
                    int cc = ep_c0 + c;
                    atomicMax(&p[cc], fenc(outb[ep_r * OB_STR + cc] + s_b[mm][cc]));
                }
            }
        }
    }

    // x_sum + counts (x reconstructed as hi+lo; err ~1e-5 relative)
    {
        int b = ids_s[ep_r];
        if (b >= 0) {
            float* dst = &g_xsum[(size_t)b * 128];
            #pragma unroll 8
            for (int c = 0; c < 64; c++) {
                int cc = ep_c0 + c;
                float v = __bfloat162float(xs_hi[ep_r * XS_STR + cc])
                        + __bfloat162float(xs_lo[ep_r * XS_STR + cc]);
                atomicAdd(&dst[cc], v);
            }
            if ((tid & 1) == 0) atomicAdd(&g_counts[b], 1.0f);
        }
    }
}

// ---------------- phase 2: centroid finalize + per-bucket Wvc GEMM ----------
__global__ void __launch_bounds__(256)
k_cent(const float* __restrict__ Wk,  const float* __restrict__ bk,
       const float* __restrict__ Wv,  const float* __restrict__ bv,
       const float* __restrict__ Wvc, const float* __restrict__ bvc) {
    __shared__ float vt[2][256];
    int tid = threadIdx.x;
    int bl = tid >> 7, c = tid & 127;
    int b = blockIdx.x * 2 + bl;

    float cnt = g_counts[b];
    float inv = 1.0f / fmaxf(cnt, 1.0f);
    const float* xs = &g_xsum[(size_t)b * 128];
    float ak = 0.0f, av = 0.0f;
    #pragma unroll 4
    for (int k = 0; k < 128; k++) {
        float xv = xs[k];
        ak = fmaf(xv, __ldg(&Wk[k * 128 + c]), ak);
        av = fmaf(xv, __ldg(&Wv[k * 128 + c]), av);
    }
    float kmean = (ak + cnt * __ldg(&bk[c])) * inv;
    float vmean = (av + cnt * __ldg(&bv[c])) * inv;
    bool ne = cnt > 0.0f;
    float kmax = ne ? fdec(g_kkey[(size_t)b * 128 + c]) : 0.0f;
    float vmax = ne ? fdec(g_vkey[(size_t)b * 128 + c]) : 0.0f;

    g_kc[(size_t)b * 256 + c]       = kmean;
    g_kc[(size_t)b * 256 + 128 + c] = kmax;
    vt[bl][c]       = vmean;
    vt[bl][128 + c] = vmax;
    __syncthreads();

    float a = 0.0f;
    #pragma unroll 4
    for (int k = 0; k < 256; k++)
        a = fmaf(vt[bl][k], __ldg(&Wvc[k * 128 + c]), a);
    g_vcomb[(size_t)b * 128 + c] = a + __ldg(&bvc[c]);
}

// ---------------- phase 3: fused gate/output chain (R6 winner, unchanged) ---
__global__ void __launch_bounds__(256, 2)
k_fused(const void* __restrict__ ids,
        const float* __restrict__ Wg1, const float* __restrict__ bg1,
        const float* __restrict__ Wg2, const float* __restrict__ bg2,
        const float* __restrict__ Wp,  const float* __restrict__ bp,
        float* __restrict__ out, int n) {
    extern __shared__ float smf[];
    float* inter = smf;                  // 64*256 ; reused as tbuf
    float* h1    = smf + 64 * 256;       // 64*128
    float* wst   = h1 + 64 * 128;        // 32*128
    __shared__ int ids_s[64];

    const bool is64 = (g_or == 0u);
    const int tid = threadIdx.x;
    const int row0 = blockIdx.x * 64;
    const float scale = 0.17677669529663687f;   // (128/4)^-0.5

    if (tid < 64) {
        int r = row0 + tid;
        ids_s[tid] = (r < n) ? get_id(ids, r, is64) : -1;
    }
    __syncthreads();

    for (int t = tid; t < 64 * 64; t += 256) {
        int r = t >> 6, c4 = t & 63;
        int b = ids_s[r];
        float4 iv = make_float4(0.f, 0.f, 0.f, 0.f);
        if (b >= 0) {
            float4 qv = ((const float4*)g_q)[(size_t)(row0 + r) * 32 + (c4 & 31)];
            float4 kc = ((const float4*)g_kc)[(size_t)b * 64 + c4];
            iv.x = qv.x * kc.x * scale; iv.y = qv.y * kc.y * scale;
            iv.z = qv.z * kc.z * scale; iv.w = qv.w * kc.w * scale;
        }
        *(float4*)&inter[r * 256 + c4 * 4] = iv;
    }

    const int rT = tid >> 5;
    const int c0 = (tid & 31) * 4;

    float acc[8][4];
    #pragma unroll
    for (int i = 0; i < 8; i++)
        #pragma unroll
        for (int j = 0; j < 4; j++) acc[i][j] = 0.0f;
    for (int kb = 0; kb < 8; kb++) {
        __syncthreads();
        for (int t = tid; t < 32 * 32; t += 256) {
            int r = t >> 5, c4 = t & 31;
            ((float4*)&wst[r * 128])[c4] = ((const float4*)Wg1)[(kb * 32 + r) * 32 + c4];
        }
        __syncthreads();
        for (int kk = 0; kk < 32; kk++) {
            int k = kb * 32 + kk;
            float4 w = *(const float4*)&wst[kk * 128 + c0];
            #pragma unroll
            for (int i = 0; i < 8; i++) {
                float xv = inter[(rT + 8 * i) * 256 + k];
                acc[i][0] = fmaf(xv, w.x, acc[i][0]);
                acc[i][1] = fmaf(xv, w.y, acc[i][1]);
                acc[i][2] = fmaf(xv, w.z, acc[i][2]);
                acc[i][3] = fmaf(xv, w.w, acc[i][3]);
            }
        }
    }
    {
        float4 b4 = *(const float4*)&bg1[c0];
        float bb[4] = {b4.x, b4.y, b4.z, b4.w};
        #pragma unroll
        for (int i = 0; i < 8; i++)
            #pragma unroll
            for (int j = 0; j < 4; j++)
                h1[(rT + 8 * i) * 128 + c0 + j] = fmaxf(acc[i][j] + bb[j], 0.0f);
    }

    float gacc[8][4];
    #pragma unroll
    for (int i = 0; i < 8; i++)
        #pragma unroll
        for (int j = 0; j < 4; j++) gacc[i][j] = 0.0f;
    for (int kb = 0; kb < 4; kb++) {
        __syncthreads();
        for (int t = tid; t < 32 * 32; t += 256) {
            int r = t >> 5, c4 = t & 31;
            ((float4*)&wst[r * 128])[c4] = ((const float4*)Wg2)[(kb * 32 + r) * 32 + c4];
        }
        __syncthreads();
        for (int kk = 0; kk < 32; kk++) {
            int k = kb * 32 + kk;
            float4 w = *(const float4*)&wst[kk * 128 + c0];
            #pragma unroll
            for (int i = 0; i < 8; i++) {
                float xv = h1[(rT + 8 * i) * 128 + k];
                gacc[i][0] = fmaf(xv, w.x, gacc[i][0]);
                gacc[i][1] = fmaf(xv, w.y, gacc[i][1]);
                gacc[i][2] = fmaf(xv, w.z, gacc[i][2]);
                gacc[i][3] = fmaf(xv, w.w, gacc[i][3]);
            }
        }
    }
    {
        float4 b4 = *(const float4*)&bg2[c0];
        float bb[4] = {b4.x, b4.y, b4.z, b4.w};
        #pragma unroll
        for (int i = 0; i < 8; i++) {
            int r = rT + 8 * i;
            int b = ids_s[r];
            float4 vc = make_float4(0.f, 0.f, 0.f, 0.f);
            if (b >= 0) vc = *(const float4*)&g_vcomb[(size_t)b * 128 + c0];
            float vca[4] = {vc.x, vc.y, vc.z, vc.w};
            #pragma unroll
            for (int j = 0; j < 4; j++) {
                float gate = 1.0f / (1.0f + __expf(-(gacc[i][j] + bb[j])));
                inter[r * 256 + c0 + j] = gate * vca[j];
            }
        }
    }

    float oacc[8][4];
    #pragma unroll
    for (int i = 0; i < 8; i++)
        #pragma unroll
        for (int j = 0; j < 4; j++) oacc[i][j] = 0.0f;
    for (int kb = 0; kb < 4; kb++) {
        __syncthreads();
        for (int t = tid; t < 32 * 32; t += 256) {
            int r = t >> 5, c4 = t & 31;
            ((float4*)&wst[r * 128])[c4] = ((const float4*)Wp)[(kb * 32 + r) * 32 + c4];
        }
        __syncthreads();
        for (int kk = 0; kk < 32; kk++) {
            int k = kb * 32 + kk;
            float4 w = *(const float4*)&wst[kk * 128 + c0];
            #pragma unroll
            for (int i = 0; i < 8; i++) {
                float xv = inter[(rT + 8 * i) * 256 + k];
                oacc[i][0] = fmaf(xv, w.x, oacc[i][0]);
                oacc[i][1] = fmaf(xv, w.y, oacc[i][1]);
                oacc[i][2] = fmaf(xv, w.z, oacc[i][2]);
                oacc[i][3] = fmaf(xv, w.w, oacc[i][3]);
            }
        }
    }
    {
        float4 b4 = *(const float4*)&bp[c0];
        float bb[4] = {b4.x, b4.y, b4.z, b4.w};
        #pragma unroll
        for (int i = 0; i < 8; i++) {
            int grow = row0 + rT + 8 * i;
            if (grow < n) {
                *(float4*)&out[(size_t)grow * 128 + c0] =
                    make_float4(oacc[i][0] + bb[0], oacc[i][1] + bb[1],
                                oacc[i][2] + bb[2], oacc[i][3] + bb[3]);
            }
        }
    }
}

// ---------------- launch ----------------------------------------------------
extern "C" void kernel_launch(void* const* d_in, const int* in_sizes, int n_in,
                              void* d_out, int out_size) {
    const float* x   = (const float*)d_in[0];
    const void*  ids = d_in[1];
    // d_in[2] = total_buckets (constant 8192, unused)
    const float *Wq = (const float*)d_in[3],  *bq = (const float*)d_in[4];
    const float *Wk = (const float*)d_in[5],  *bk = (const float*)d_in[6];
    const float *Wv = (const float*)d_in[7],  *bv = (const float*)d_in[8];
    const float *Wg1 = (const float*)d_in[9], *bg1 = (const float*)d_in[10];
    const float *Wg2 = (const float*)d_in[11], *bg2 = (const float*)d_in[12];
    const float *Wvc = (const float*)d_in[13], *bvc = (const float*)d_in[14];
    const float *Wp  = (const float*)d_in[15], *bp  = (const float*)d_in[16];
    float* out = (float*)d_out;

    const int n = in_sizes[0] / CC;
    const int SM_FUSED = (64 * 256 + 64 * 128 + 32 * 128) * 4;     // 114688

    static int smem_set = 0;
    if (!smem_set) {
        cudaFuncSetAttribute(k_qkv,   cudaFuncAttributeMaxDynamicSharedMemorySize, SM_QKV_BYTES);
        cudaFuncSetAttribute(k_fused, cudaFuncAttributeMaxDynamicSharedMemorySize, SM_FUSED);
        smem_set = 1;
    }

    k_init<<<512, 256>>>();
    k_detect<<<256, 256>>>((const unsigned*)ids, in_sizes[1]);

    int g1 = (n + 127) / 128;
    k_qkv<<<g1, 256, SM_QKV_BYTES>>>(x, ids, Wq, bq, Wk, bk, Wv, bv, n);

    k_cent<<<BKT / 2, 256>>>(Wk, bk, Wv, bv, Wvc, bvc);

    int g3 = (n + 63) / 64;
    k_fused<<<g3, 256, SM_FUSED>>>(ids, Wg1, bg1, Wg2, bg2, Wp, bp, out, n);
}